// round 10
// baseline (speedup 1.0000x reference)
#include <cuda_runtime.h>

#define NN 10000
#define EE 160000
#define GG 64
#define HH 32
#define WIDTH 64   // ELL width; degree ~ Binomial(160k, 1e-4), P(>=64) ~ 1e-20

// ---- scratch (device globals; referenced ONLY in device code) ----
__device__ float  d_deg[NN];            // 1 + sum of incoming edge weights
__device__ int    d_count[NN];          // per-dst edge count / ELL fill cursor
__device__ float2 d_ell[NN * WIDTH];    // after k_norm: {src as int bits, full norm}; padded slots {0,0}
__device__ float  d_xt[NN * GG];        // x transposed (N, G)
__device__ float  d_zt[NN * GG];        // layer-1 output transposed
__device__ float  d_ot[NN * GG];        // layer-2 output transposed

// ---- K_A: fused init (deg=1, count=0) + transpose x (G,N) -> (N,G) ----
__global__ void k_prep(const float* __restrict__ x) {
    int flat = (blockIdx.y * gridDim.x + blockIdx.x) * 1024 + threadIdx.y * 32 + threadIdx.x;
    if (flat < NN) { d_deg[flat] = 1.0f; d_count[flat] = 0; }

    __shared__ float t[32][33];
    int n0 = blockIdx.x * 32, g0 = blockIdx.y * 32;
    int tx = threadIdx.x, ty = threadIdx.y;
    int n = n0 + tx, g = g0 + ty;
    if (n < NN) t[ty][tx] = x[g * NN + n];
    __syncthreads();
    n = n0 + ty; g = g0 + tx;
    if (n < NN) d_xt[n * GG + g] = t[tx][ty];
}

// ---- K_B: single edge pass: ELL build + degree accumulate (2 edges/thread) ----
__global__ void k_build(const int* __restrict__ ei, const float* __restrict__ w) {
    int i = blockIdx.x * blockDim.x + threadIdx.x;
    if (i < EE / 2) {
        int2   s2 = ((const int2*)ei)[i];            // src pair
        int2   d2 = ((const int2*)ei)[EE / 2 + i];   // dst pair (dst base = ei+EE)
        float2 w2 = ((const float2*)w)[i];

        int p0 = atomicAdd(&d_count[d2.x], 1);
        if (p0 < WIDTH) d_ell[d2.x * WIDTH + p0] = make_float2(__int_as_float(s2.x), w2.x);
        atomicAdd(&d_deg[d2.x], w2.x);

        int p1 = atomicAdd(&d_count[d2.y], 1);
        if (p1 < WIDTH) d_ell[d2.y * WIDTH + p1] = make_float2(__int_as_float(s2.y), w2.y);
        atomicAdd(&d_deg[d2.y], w2.y);
    }
}

// ---- K_C: pre-normalize ELL entries: w -> dinv[src]*w*dinv[dst] ----
__global__ void k_norm() {
    int row = blockIdx.x * 4 + (threadIdx.x >> 6);
    int j   = threadIdx.x & 63;
    if (row < NN && j < d_count[row]) {
        float2 p = d_ell[row * WIDTH + j];
        int s = __float_as_int(p.x);
        d_ell[row * WIDTH + j].y = p.y * rsqrtf(d_deg[s]) * rsqrtf(d_deg[row]);
    }
}

// ---- SpMV: TWO warps per row, each owning 32 of the 64 replicas ----
// 20k warps total (2x parallelism vs warp-per-row). Lane carries ONE scalar.
// ELL metadata register-staged per warp (2 coalesced LDG.64) and broadcast via
// shfl; 8 independent LDG.32 gathers (128B each) per chunk, addresses never
// wait on an in-flight load. Padded slots are {0,0} -> zero contribution.
template <int LAYER>
__global__ void __launch_bounds__(256, 6) k_spmv(
        const float* __restrict__ Wa, const float* __restrict__ ba,
        const float* __restrict__ Wb, const float* __restrict__ b2) {
    __shared__ float sW1[HH], sB1[HH], sW2[HH];
    if (LAYER == 1) {
        if (threadIdx.x < HH) {
            sW1[threadIdx.x] = Wa[threadIdx.x];
            sB1[threadIdx.x] = ba[threadIdx.x];
            sW2[threadIdx.x] = Wb[threadIdx.x];
        }
        __syncthreads();
    }

    int gw   = (blockIdx.x * blockDim.x + threadIdx.x) >> 5;   // 0 .. 2*NN-1
    int row  = gw >> 1;
    int col  = ((gw & 1) << 5) + (threadIdx.x & 31);           // replica index 0..63
    int lane = threadIdx.x & 31;
    const float* in  = (LAYER == 1 ? d_xt : d_zt);
    float*       ou  = (LAYER == 1 ? d_zt : d_ot);

    const float2* ell2 = d_ell + row * WIDTH;
    float2 elo = ell2[lane];          // slots 0..31   (coalesced)
    float2 ehi = ell2[32 + lane];     // slots 32..63  (coalesced, independent)

    float sn  = 1.0f / d_deg[row];    // self-loop norm = dinv^2
    float acc = sn * in[row * GG + col];

    int cnt = min(d_count[row], WIDTH);
    for (int base = 0; base < cnt; base += 8) {
        float ex = (base & 32) ? ehi.x : elo.x;   // uniform half-select, branchless
        float ey = (base & 32) ? ehi.y : elo.y;
        int b = base & 31;                         // b in {0,8,16,24}
        int   s0 = __float_as_int(__shfl_sync(0xffffffffu, ex, b + 0));
        int   s1 = __float_as_int(__shfl_sync(0xffffffffu, ex, b + 1));
        int   s2 = __float_as_int(__shfl_sync(0xffffffffu, ex, b + 2));
        int   s3 = __float_as_int(__shfl_sync(0xffffffffu, ex, b + 3));
        int   s4 = __float_as_int(__shfl_sync(0xffffffffu, ex, b + 4));
        int   s5 = __float_as_int(__shfl_sync(0xffffffffu, ex, b + 5));
        int   s6 = __float_as_int(__shfl_sync(0xffffffffu, ex, b + 6));
        int   s7 = __float_as_int(__shfl_sync(0xffffffffu, ex, b + 7));
        float n0 = __shfl_sync(0xffffffffu, ey, b + 0);
        float n1 = __shfl_sync(0xffffffffu, ey, b + 1);
        float n2 = __shfl_sync(0xffffffffu, ey, b + 2);
        float n3 = __shfl_sync(0xffffffffu, ey, b + 3);
        float n4 = __shfl_sync(0xffffffffu, ey, b + 4);
        float n5 = __shfl_sync(0xffffffffu, ey, b + 5);
        float n6 = __shfl_sync(0xffffffffu, ey, b + 6);
        float n7 = __shfl_sync(0xffffffffu, ey, b + 7);
        // 8 independent 128B gathers; addresses are register-only
        float v0 = in[s0 * GG + col];
        float v1 = in[s1 * GG + col];
        float v2 = in[s2 * GG + col];
        float v3 = in[s3 * GG + col];
        float v4 = in[s4 * GG + col];
        float v5 = in[s5 * GG + col];
        float v6 = in[s6 * GG + col];
        float v7 = in[s7 * GG + col];
        acc = fmaf(n0, v0, acc);
        acc = fmaf(n1, v1, acc);
        acc = fmaf(n2, v2, acc);
        acc = fmaf(n3, v3, acc);
        acc = fmaf(n4, v4, acc);
        acc = fmaf(n5, v5, acc);
        acc = fmaf(n6, v6, acc);
        acc = fmaf(n7, v7, acc);
    }

    float res;
    if (LAYER == 1) {
        float z0 = 0.f;
        #pragma unroll
        for (int j = 0; j < HH; j++)
            z0 += fmaxf(fmaf(acc, sW1[j], sB1[j]), 0.f) * sW2[j];
        res = z0;
    } else {
        res = acc + __ldg(b2);
    }
    ou[row * GG + col] = res;
}

// ---- K_F: transpose out (N,G)->(G,N) fused with mask merge (mask is int32) ----
__global__ void k_out(const float* __restrict__ x, const int* __restrict__ mask,
                      float* __restrict__ out) {
    __shared__ float t[32][33];
    int n0 = blockIdx.x * 32, g0 = blockIdx.y * 32;
    int tx = threadIdx.x, ty = threadIdx.y;
    int n = n0 + ty, g = g0 + tx;
    if (n < NN) t[ty][tx] = d_ot[n * GG + g];
    __syncthreads();
    n = n0 + tx; g = g0 + ty;
    if (n < NN) {
        int idx = g * NN + n;
        out[idx] = mask[idx] ? x[idx] : t[tx][ty];
    }
}

extern "C" void kernel_launch(void* const* d_in, const int* in_sizes, int n_in,
                              void* d_out, int out_size) {
    const float* x    = (const float*)d_in[0];
    const int*   mask = (const int*)d_in[1];      // jax bool -> int32 on the wire
    const int*   ei   = (const int*)d_in[2];
    const float* w    = (const float*)d_in[3];
    const float* W1   = (const float*)d_in[4];
    const float* b1   = (const float*)d_in[5];
    const float* W2   = (const float*)d_in[6];
    const float* b2   = (const float*)d_in[7];
    float*       out  = (float*)d_out;

    dim3 tb(32, 32);
    dim3 tg((NN + 31) / 32, GG / 32);
    k_prep<<<tg, tb>>>(x);
    k_build<<<(EE / 2 + 255) / 256, 256>>>(ei, w);
    k_norm<<<(NN + 3) / 4, 256>>>();
    k_spmv<1><<<2 * NN / 8, 256>>>(W1, b1, W2, b2);   // 2 warps/row, 8 warps/block
    k_spmv<2><<<2 * NN / 8, 256>>>(W1, b1, W2, b2);
    k_out<<<tg, tb>>>(x, mask, out);
}

// round 11
// speedup vs baseline: 1.1165x; 1.1165x over previous
#include <cuda_runtime.h>

#define NN 10000
#define EE 160000
#define GG 64
#define HH 32
#define WIDTH 64   // ELL width; degree ~ Binomial(160k, 1e-4), P(>=64) ~ 1e-20

// ---- scratch (device globals; referenced ONLY in device code) ----
__device__ float  d_deg[NN];            // 1 + sum of incoming edge weights
__device__ int    d_count[NN];          // per-dst edge count / ELL fill cursor
__device__ float2 d_ell[NN * WIDTH];    // after k_norm: {src as int bits, full norm}; padded slots {0,0}
__device__ float  d_xt[NN * GG];        // x transposed (N, G)
__device__ float  d_zt[NN * GG];        // layer-1 output transposed
__device__ float  d_ot[NN * GG];        // layer-2 output transposed

// ---- K_A: fused init (deg=1, count=0) + transpose x (G,N) -> (N,G) ----
__global__ void k_prep(const float* __restrict__ x) {
    int flat = (blockIdx.y * gridDim.x + blockIdx.x) * 1024 + threadIdx.y * 32 + threadIdx.x;
    if (flat < NN) { d_deg[flat] = 1.0f; d_count[flat] = 0; }

    __shared__ float t[32][33];
    int n0 = blockIdx.x * 32, g0 = blockIdx.y * 32;
    int tx = threadIdx.x, ty = threadIdx.y;
    int n = n0 + tx, g = g0 + ty;
    if (n < NN) t[ty][tx] = x[g * NN + n];
    __syncthreads();
    n = n0 + ty; g = g0 + tx;
    if (n < NN) d_xt[n * GG + g] = t[tx][ty];
}

// ---- K_B: single edge pass: ELL build + degree accumulate (2 edges/thread) ----
__global__ void k_build(const int* __restrict__ ei, const float* __restrict__ w) {
    int i = blockIdx.x * blockDim.x + threadIdx.x;
    if (i < EE / 2) {
        int2   s2 = ((const int2*)ei)[i];            // src pair
        int2   d2 = ((const int2*)ei)[EE / 2 + i];   // dst pair (dst base = ei+EE)
        float2 w2 = ((const float2*)w)[i];

        int p0 = atomicAdd(&d_count[d2.x], 1);
        if (p0 < WIDTH) d_ell[d2.x * WIDTH + p0] = make_float2(__int_as_float(s2.x), w2.x);
        atomicAdd(&d_deg[d2.x], w2.x);

        int p1 = atomicAdd(&d_count[d2.y], 1);
        if (p1 < WIDTH) d_ell[d2.y * WIDTH + p1] = make_float2(__int_as_float(s2.y), w2.y);
        atomicAdd(&d_deg[d2.y], w2.y);
    }
}

// ---- K_C: pre-normalize ELL entries: w -> dinv[src]*w*dinv[dst] ----
__global__ void k_norm() {
    int row = blockIdx.x * 4 + (threadIdx.x >> 6);
    int j   = threadIdx.x & 63;
    if (row < NN && j < d_count[row]) {
        float2 p = d_ell[row * WIDTH + j];
        int s = __float_as_int(p.x);
        d_ell[row * WIDTH + j].y = p.y * rsqrtf(d_deg[s]) * rsqrtf(d_deg[row]);
    }
}

// ---- static 16-edge block: 16 shfl-broadcasts -> 16 independent gathers -> FMAs ----
// All indices compile-time => register arrays; ptxas can front-batch all 16 gathers.
__device__ __forceinline__ void chunk16(const float2* __restrict__ in2, int lane,
                                        float2& acc, float ex, float ey, int lb) {
    int   s[16];
    float n[16];
    #pragma unroll
    for (int k = 0; k < 16; k++) {
        s[k] = __float_as_int(__shfl_sync(0xffffffffu, ex, lb + k));
        n[k] = __shfl_sync(0xffffffffu, ey, lb + k);
    }
    float2 v[16];
    #pragma unroll
    for (int k = 0; k < 16; k++) v[k] = in2[s[k] * 32 + lane];
    #pragma unroll
    for (int k = 0; k < 16; k++) {
        acc.x = fmaf(n[k], v[k].x, acc.x);
        acc.y = fmaf(n[k], v[k].y, acc.y);
    }
}

// ---- SpMV: warp-per-row, 2 replicas/lane, register-staged ELL, STATIC chunks ----
// Lane l holds ELL slots l and l+32 (2 coalesced LDG.64 = one metadata window).
// Four static 16-edge blocks guarded by warp-uniform conditions; padded slots
// are {0,0} so over-processing a partial block contributes exactly zero.
template <int LAYER>
__global__ void k_spmv(const float* __restrict__ Wa, const float* __restrict__ ba,
                       const float* __restrict__ Wb, const float* __restrict__ b2) {
    __shared__ float sW1[HH], sB1[HH], sW2[HH];
    if (LAYER == 1) {
        if (threadIdx.x < HH) {
            sW1[threadIdx.x] = Wa[threadIdx.x];
            sB1[threadIdx.x] = ba[threadIdx.x];
            sW2[threadIdx.x] = Wb[threadIdx.x];
        }
        __syncthreads();
    }

    int row  = (blockIdx.x * blockDim.x + threadIdx.x) >> 5;   // grid = exactly NN warps
    int lane = threadIdx.x & 31;
    const float2* in2 = (const float2*)(LAYER == 1 ? d_xt : d_zt);
    float2*       ou2 = (float2*)      (LAYER == 1 ? d_zt : d_ot);

    const float2* ell2 = d_ell + row * WIDTH;
    float2 elo = ell2[lane];          // slots 0..31   (coalesced 256B)
    float2 ehi = ell2[32 + lane];     // slots 32..63  (coalesced 256B, independent)

    float sn = 1.0f / d_deg[row];     // self-loop norm = dinv^2
    float2 xs = in2[row * 32 + lane];
    float2 acc = make_float2(sn * xs.x, sn * xs.y);

    int cnt = min(d_count[row], WIDTH);
    chunk16(in2, lane, acc, elo.x, elo.y, 0);                   // edges 0..15 (deg>=1 w/ self? deg>0 rows dominate; zero-pad safe anyway)
    if (cnt > 16) chunk16(in2, lane, acc, elo.x, elo.y, 16);    // edges 16..31
    if (cnt > 32) chunk16(in2, lane, acc, ehi.x, ehi.y, 0);     // edges 32..47
    if (cnt > 48) chunk16(in2, lane, acc, ehi.x, ehi.y, 16);    // edges 48..63

    float2 res;
    if (LAYER == 1) {
        float z0 = 0.f, z1 = 0.f;
        #pragma unroll
        for (int j = 0; j < HH; j++) {
            z0 += fmaxf(fmaf(acc.x, sW1[j], sB1[j]), 0.f) * sW2[j];
            z1 += fmaxf(fmaf(acc.y, sW1[j], sB1[j]), 0.f) * sW2[j];
        }
        res = make_float2(z0, z1);
    } else {
        float bb = __ldg(b2);
        res = make_float2(acc.x + bb, acc.y + bb);
    }
    ou2[row * 32 + lane] = res;
}

// ---- K_F: transpose out (N,G)->(G,N) fused with mask merge (mask is int32) ----
__global__ void k_out(const float* __restrict__ x, const int* __restrict__ mask,
                      float* __restrict__ out) {
    __shared__ float t[32][33];
    int n0 = blockIdx.x * 32, g0 = blockIdx.y * 32;
    int tx = threadIdx.x, ty = threadIdx.y;
    int n = n0 + ty, g = g0 + tx;
    if (n < NN) t[ty][tx] = d_ot[n * GG + g];
    __syncthreads();
    n = n0 + tx; g = g0 + ty;
    if (n < NN) {
        int idx = g * NN + n;
        out[idx] = mask[idx] ? x[idx] : t[tx][ty];
    }
}

extern "C" void kernel_launch(void* const* d_in, const int* in_sizes, int n_in,
                              void* d_out, int out_size) {
    const float* x    = (const float*)d_in[0];
    const int*   mask = (const int*)d_in[1];      // jax bool -> int32 on the wire
    const int*   ei   = (const int*)d_in[2];
    const float* w    = (const float*)d_in[3];
    const float* W1   = (const float*)d_in[4];
    const float* b1   = (const float*)d_in[5];
    const float* W2   = (const float*)d_in[6];
    const float* b2   = (const float*)d_in[7];
    float*       out  = (float*)d_out;

    dim3 tb(32, 32);
    dim3 tg((NN + 31) / 32, GG / 32);
    k_prep<<<tg, tb>>>(x);
    k_build<<<(EE / 2 + 255) / 256, 256>>>(ei, w);
    k_norm<<<(NN + 3) / 4, 256>>>();
    k_spmv<1><<<NN / 8, 256>>>(W1, b1, W2, b2);   // warp-per-row, 8 warps/block
    k_spmv<2><<<NN / 8, 256>>>(W1, b1, W2, b2);
    k_out<<<tg, tb>>>(x, mask, out);
}

// round 12
// speedup vs baseline: 1.2316x; 1.1030x over previous
#include <cuda_runtime.h>

#define NN 10000
#define EE 160000
#define GG 64
#define HH 32
#define WIDTH 64   // ELL width; degree ~ Binomial(160k, 1e-4), P(>=64) ~ 1e-20

// ---- scratch (device globals; referenced ONLY in device code) ----
__device__ float  d_deg[NN];            // 1 + sum of incoming edge weights
__device__ int    d_count[NN];          // per-dst edge count / ELL fill cursor
__device__ float2 d_ell[NN * WIDTH];    // {src bits, w}; spmv1 normalizes in place; pad slots stay {0,0}
__device__ float  d_xt[NN * GG];        // x transposed (N, G)
__device__ float  d_zt[NN * GG];        // layer-1 output transposed
__device__ float  d_ot[NN * GG];        // layer-2 output transposed

// ---- K_A: fused init (deg=1, count=0) + transpose x (G,N) -> (N,G) ----
__global__ void k_prep(const float* __restrict__ x) {
    int flat = (blockIdx.y * gridDim.x + blockIdx.x) * 1024 + threadIdx.y * 32 + threadIdx.x;
    if (flat < NN) { d_deg[flat] = 1.0f; d_count[flat] = 0; }

    __shared__ float t[32][33];
    int n0 = blockIdx.x * 32, g0 = blockIdx.y * 32;
    int tx = threadIdx.x, ty = threadIdx.y;
    int n = n0 + tx, g = g0 + ty;
    if (n < NN) t[ty][tx] = x[g * NN + n];
    __syncthreads();
    n = n0 + ty; g = g0 + tx;
    if (n < NN) d_xt[n * GG + g] = t[tx][ty];
}

// ---- K_B: single edge pass: ELL build + degree accumulate (1 edge/thread) ----
__global__ void k_build(const int* __restrict__ ei, const float* __restrict__ w) {
    int i = blockIdx.x * blockDim.x + threadIdx.x;
    if (i < EE) {
        int   s  = ei[i];
        int   d  = ei[EE + i];
        float ww = w[i];
        int p = atomicAdd(&d_count[d], 1);
        if (p < WIDTH) d_ell[d * WIDTH + p] = make_float2(__int_as_float(s), ww);
        atomicAdd(&d_deg[d], ww);      // no return use -> REDG
    }
}

// ---- static 8-edge block: 8 shfl-broadcasts -> 8 independent gathers -> FMAs ----
__device__ __forceinline__ void chunk8(const float2* __restrict__ in2, int lane,
                                       float2& acc, float ex, float ey, int lb) {
    int   s[8];
    float n[8];
    #pragma unroll
    for (int k = 0; k < 8; k++) {
        s[k] = __float_as_int(__shfl_sync(0xffffffffu, ex, lb + k));
        n[k] = __shfl_sync(0xffffffffu, ey, lb + k);
    }
    float2 v[8];
    #pragma unroll
    for (int k = 0; k < 8; k++) v[k] = in2[s[k] * 32 + lane];
    #pragma unroll
    for (int k = 0; k < 8; k++) {
        acc.x = fmaf(n[k], v[k].x, acc.x);
        acc.y = fmaf(n[k], v[k].y, acc.y);
    }
}

// ---- SpMV: warp-per-row, 2 replicas/lane, register-staged ELL, static chunk8 x8 ----
// LAYER 1 also performs the gcn normalization in registers (each lane normalizes
// its own staged slots) and writes the normalized entries back for LAYER 2.
// ELL upper half (slots 32..63) is touched only when cnt > 32 (~0.01% of rows).
template <int LAYER>
__global__ void k_spmv(const float* __restrict__ Wa, const float* __restrict__ ba,
                       const float* __restrict__ Wb, const float* __restrict__ b2) {
    __shared__ float sW1[HH], sB1[HH], sW2[HH];
    if (LAYER == 1) {
        if (threadIdx.x < HH) {
            sW1[threadIdx.x] = Wa[threadIdx.x];
            sB1[threadIdx.x] = ba[threadIdx.x];
            sW2[threadIdx.x] = Wb[threadIdx.x];
        }
        __syncthreads();
    }

    int row  = (blockIdx.x * blockDim.x + threadIdx.x) >> 5;   // grid = exactly NN warps
    int lane = threadIdx.x & 31;
    const float2* in2 = (const float2*)(LAYER == 1 ? d_xt : d_zt);
    float2*       ou2 = (float2*)      (LAYER == 1 ? d_zt : d_ot);

    float2* ell2 = d_ell + row * WIDTH;
    int cnt = min(d_count[row], WIDTH);

    float2 elo = ell2[lane];                       // slots 0..31 (coalesced 256B)
    float2 ehi = make_float2(0.f, 0.f);
    if (cnt > 32) ehi = ell2[32 + lane];           // rare upper half

    float dr = rsqrtf(d_deg[row]);
    float sn = dr * dr;                            // self-loop norm = 1/deg

    if (LAYER == 1) {
        // normalize staged entries in registers; pad slots: 0 * anything = 0
        elo.y *= rsqrtf(d_deg[__float_as_int(elo.x)]) * dr;
        ell2[lane] = elo;                          // write back for LAYER 2
        if (cnt > 32) {
            ehi.y *= rsqrtf(d_deg[__float_as_int(ehi.x)]) * dr;
            ell2[32 + lane] = ehi;
        }
    }

    float2 xs = in2[row * 32 + lane];
    float2 acc = make_float2(sn * xs.x, sn * xs.y);

    if (cnt > 0)  chunk8(in2, lane, acc, elo.x, elo.y, 0);
    if (cnt > 8)  chunk8(in2, lane, acc, elo.x, elo.y, 8);
    if (cnt > 16) chunk8(in2, lane, acc, elo.x, elo.y, 16);
    if (cnt > 24) chunk8(in2, lane, acc, elo.x, elo.y, 24);
    if (cnt > 32) chunk8(in2, lane, acc, ehi.x, ehi.y, 0);
    if (cnt > 40) chunk8(in2, lane, acc, ehi.x, ehi.y, 8);
    if (cnt > 48) chunk8(in2, lane, acc, ehi.x, ehi.y, 16);
    if (cnt > 56) chunk8(in2, lane, acc, ehi.x, ehi.y, 24);

    float2 res;
    if (LAYER == 1) {
        float z0 = 0.f, z1 = 0.f;
        #pragma unroll
        for (int j = 0; j < HH; j++) {
            z0 += fmaxf(fmaf(acc.x, sW1[j], sB1[j]), 0.f) * sW2[j];
            z1 += fmaxf(fmaf(acc.y, sW1[j], sB1[j]), 0.f) * sW2[j];
        }
        res = make_float2(z0, z1);
    } else {
        float bb = __ldg(b2);
        res = make_float2(acc.x + bb, acc.y + bb);
    }
    ou2[row * 32 + lane] = res;
}

// ---- K_F: transpose out (N,G)->(G,N) fused with mask merge (mask is int32) ----
__global__ void k_out(const float* __restrict__ x, const int* __restrict__ mask,
                      float* __restrict__ out) {
    __shared__ float t[32][33];
    int n0 = blockIdx.x * 32, g0 = blockIdx.y * 32;
    int tx = threadIdx.x, ty = threadIdx.y;
    int n = n0 + ty, g = g0 + tx;
    if (n < NN) t[ty][tx] = d_ot[n * GG + g];
    __syncthreads();
    n = n0 + tx; g = g0 + ty;
    if (n < NN) {
        int idx = g * NN + n;
        out[idx] = mask[idx] ? x[idx] : t[tx][ty];
    }
}

extern "C" void kernel_launch(void* const* d_in, const int* in_sizes, int n_in,
                              void* d_out, int out_size) {
    const float* x    = (const float*)d_in[0];
    const int*   mask = (const int*)d_in[1];      // jax bool -> int32 on the wire
    const int*   ei   = (const int*)d_in[2];
    const float* w    = (const float*)d_in[3];
    const float* W1   = (const float*)d_in[4];
    const float* b1   = (const float*)d_in[5];
    const float* W2   = (const float*)d_in[6];
    const float* b2   = (const float*)d_in[7];
    float*       out  = (float*)d_out;

    dim3 tb(32, 32);
    dim3 tg((NN + 31) / 32, GG / 32);
    k_prep<<<tg, tb>>>(x);
    k_build<<<(EE + 255) / 256, 256>>>(ei, w);
    k_spmv<1><<<NN / 8, 256>>>(W1, b1, W2, b2);   // warp-per-row; also normalizes ELL
    k_spmv<2><<<NN / 8, 256>>>(W1, b1, W2, b2);
    k_out<<<tg, tb>>>(x, mask, out);
}

// round 13
// speedup vs baseline: 1.2529x; 1.0173x over previous
#include <cuda_runtime.h>

#define NN 10000
#define EE 160000
#define GG 64
#define HH 32
#define WIDTH 64   // ELL width; degree ~ Binomial(160k, 1e-4), P(>=64) ~ 1e-20

// ---- scratch (device globals; referenced ONLY in device code) ----
__device__ float  d_deg[NN];            // 1 + sum of incoming edge weights
__device__ int    d_count[NN];          // per-dst edge count / ELL fill cursor
__device__ float2 d_ell[NN * WIDTH];    // {src bits, w}; spmv1 normalizes in place; pad slots stay {0,0}
__device__ float  d_xt[NN * GG];        // x transposed (N, G)
__device__ float  d_zt[NN * GG];        // layer-1 output transposed
__device__ float  d_ot[NN * GG];        // layer-2 output transposed

// ---- K_A: fused init (deg=1, count=0) + transpose x (G,N) -> (N,G) ----
__global__ void k_prep(const float* __restrict__ x) {
    int flat = (blockIdx.y * gridDim.x + blockIdx.x) * 1024 + threadIdx.y * 32 + threadIdx.x;
    if (flat < NN) { d_deg[flat] = 1.0f; d_count[flat] = 0; }

    __shared__ float t[32][33];
    int n0 = blockIdx.x * 32, g0 = blockIdx.y * 32;
    int tx = threadIdx.x, ty = threadIdx.y;
    int n = n0 + tx, g = g0 + ty;
    if (n < NN) t[ty][tx] = x[g * NN + n];
    __syncthreads();
    n = n0 + ty; g = g0 + tx;
    if (n < NN) d_xt[n * GG + g] = t[tx][ty];
}

// ---- K_B: single edge pass: ELL build + degree accumulate (1 edge/thread) ----
__global__ void k_build(const int* __restrict__ ei, const float* __restrict__ w) {
    int i = blockIdx.x * blockDim.x + threadIdx.x;
    if (i < EE) {
        int   s  = ei[i];
        int   d  = ei[EE + i];
        float ww = w[i];
        int p = atomicAdd(&d_count[d], 1);
        if (p < WIDTH) d_ell[d * WIDTH + p] = make_float2(__int_as_float(s), ww);
        atomicAdd(&d_deg[d], ww);      // no return use -> REDG
    }
}

// ---- static 8-edge block: 8 shfl-broadcasts -> 8 independent gathers -> FMAs ----
__device__ __forceinline__ void chunk8(const float2* __restrict__ in2, int lane,
                                       float2& acc, float ex, float ey, int lb) {
    int   s[8];
    float n[8];
    #pragma unroll
    for (int k = 0; k < 8; k++) {
        s[k] = __float_as_int(__shfl_sync(0xffffffffu, ex, lb + k));
        n[k] = __shfl_sync(0xffffffffu, ey, lb + k);
    }
    float2 v[8];
    #pragma unroll
    for (int k = 0; k < 8; k++) v[k] = in2[s[k] * 32 + lane];
    #pragma unroll
    for (int k = 0; k < 8; k++) {
        acc.x = fmaf(n[k], v[k].x, acc.x);
        acc.y = fmaf(n[k], v[k].y, acc.y);
    }
}

// ---- SpMV: warp-per-row, 2 replicas/lane, register-staged ELL ----
// Low half (slots 0..31) is processed UNCONDITIONALLY, branch-free: padded
// slots are {0,0}, and their gathers hit in2[0..31] -- one L1-resident 256B
// line -- so waste is ~free while all 32 gathers share one latency window.
// Hi half (slots 32..63) guarded; ~0.01% of rows take it.
// LAYER 1 additionally performs the gcn normalization in registers and writes
// the normalized ELL back for LAYER 2.
template <int LAYER>
__global__ void k_spmv(const float* __restrict__ Wa, const float* __restrict__ ba,
                       const float* __restrict__ Wb, const float* __restrict__ b2) {
    __shared__ float sW1[HH], sB1[HH], sW2[HH];
    if (LAYER == 1) {
        if (threadIdx.x < HH) {
            sW1[threadIdx.x] = Wa[threadIdx.x];
            sB1[threadIdx.x] = ba[threadIdx.x];
            sW2[threadIdx.x] = Wb[threadIdx.x];
        }
        __syncthreads();
    }

    int row  = (blockIdx.x * blockDim.x + threadIdx.x) >> 5;   // grid = exactly NN warps
    int lane = threadIdx.x & 31;
    const float2* in2 = (const float2*)(LAYER == 1 ? d_xt : d_zt);
    float2*       ou2 = (float2*)      (LAYER == 1 ? d_zt : d_ot);

    float2* ell2 = d_ell + row * WIDTH;
    int cnt = d_count[row];

    float2 elo = ell2[lane];                       // slots 0..31 (coalesced 256B)

    float dr = rsqrtf(d_deg[row]);
    float sn = dr * dr;                            // self-loop norm = 1/deg

    if (LAYER == 1) {
        // normalize staged entries in registers; pad slots: 0 * anything = 0
        elo.y *= rsqrtf(d_deg[__float_as_int(elo.x)]) * dr;
        ell2[lane] = elo;                          // write back for LAYER 2
    }

    float2 xs = in2[row * 32 + lane];
    float2 acc = make_float2(sn * xs.x, sn * xs.y);

    // branch-free low half: 4 straight-line chunk8s (32 gathers, one window)
    chunk8(in2, lane, acc, elo.x, elo.y, 0);
    chunk8(in2, lane, acc, elo.x, elo.y, 8);
    chunk8(in2, lane, acc, elo.x, elo.y, 16);
    chunk8(in2, lane, acc, elo.x, elo.y, 24);

    if (cnt > 32) {                                // rare tail (P ~ 1e-4)
        float2 ehi = ell2[32 + lane];
        if (LAYER == 1) {
            ehi.y *= rsqrtf(d_deg[__float_as_int(ehi.x)]) * dr;
            ell2[32 + lane] = ehi;
        }
        chunk8(in2, lane, acc, ehi.x, ehi.y, 0);
        chunk8(in2, lane, acc, ehi.x, ehi.y, 8);
        chunk8(in2, lane, acc, ehi.x, ehi.y, 16);
        chunk8(in2, lane, acc, ehi.x, ehi.y, 24);
    }

    float2 res;
    if (LAYER == 1) {
        float z0 = 0.f, z1 = 0.f;
        #pragma unroll
        for (int j = 0; j < HH; j++) {
            z0 += fmaxf(fmaf(acc.x, sW1[j], sB1[j]), 0.f) * sW2[j];
            z1 += fmaxf(fmaf(acc.y, sW1[j], sB1[j]), 0.f) * sW2[j];
        }
        res = make_float2(z0, z1);
    } else {
        float bb = __ldg(b2);
        res = make_float2(acc.x + bb, acc.y + bb);
    }
    ou2[row * 32 + lane] = res;
}

// ---- K_F: transpose out (N,G)->(G,N) fused with mask merge (mask is int32) ----
__global__ void k_out(const float* __restrict__ x, const int* __restrict__ mask,
                      float* __restrict__ out) {
    __shared__ float t[32][33];
    int n0 = blockIdx.x * 32, g0 = blockIdx.y * 32;
    int tx = threadIdx.x, ty = threadIdx.y;
    int n = n0 + ty, g = g0 + tx;
    if (n < NN) t[ty][tx] = d_ot[n * GG + g];
    __syncthreads();
    n = n0 + tx; g = g0 + ty;
    if (n < NN) {
        int idx = g * NN + n;
        out[idx] = mask[idx] ? x[idx] : t[tx][ty];
    }
}

extern "C" void kernel_launch(void* const* d_in, const int* in_sizes, int n_in,
                              void* d_out, int out_size) {
    const float* x    = (const float*)d_in[0];
    const int*   mask = (const int*)d_in[1];      // jax bool -> int32 on the wire
    const int*   ei   = (const int*)d_in[2];
    const float* w    = (const float*)d_in[3];
    const float* W1   = (const float*)d_in[4];
    const float* b1   = (const float*)d_in[5];
    const float* W2   = (const float*)d_in[6];
    const float* b2   = (const float*)d_in[7];
    float*       out  = (float*)d_out;

    dim3 tb(32, 32);
    dim3 tg((NN + 31) / 32, GG / 32);
    k_prep<<<tg, tb>>>(x);
    k_build<<<(EE + 255) / 256, 256>>>(ei, w);
    k_spmv<1><<<NN / 8, 256>>>(W1, b1, W2, b2);   // warp-per-row; also normalizes ELL
    k_spmv<2><<<NN / 8, 256>>>(W1, b1, W2, b2);
    k_out<<<tg, tb>>>(x, mask, out);
}

// round 14
// speedup vs baseline: 1.2541x; 1.0010x over previous
#include <cuda_runtime.h>

#define NN 10000
#define EE 160000
#define GG 64
#define HH 32
#define WIDTH 64   // ELL width; degree ~ Binomial(160k, 1e-4), P(>=64) ~ 1e-20

// ---- scratch (device globals; referenced ONLY in device code) ----
__device__ float  d_deg[NN];            // 1 + sum of incoming edge weights
__device__ int    d_count[NN];          // per-dst edge count / ELL fill cursor
__device__ float2 d_ell[NN * WIDTH];    // {src bits, w}; spmv1 normalizes in place; pad slots stay {0,0}
__device__ float  d_xt[NN * GG];        // x transposed (N, G)
__device__ float  d_zt[NN * GG];        // layer-1 output transposed
__device__ float  d_ot[NN * GG];        // layer-2 output transposed

// ---- K_A: fused init (deg=1, count=0) + transpose x (G,N) -> (N,G) ----
__global__ void k_prep(const float* __restrict__ x) {
    int flat = (blockIdx.y * gridDim.x + blockIdx.x) * 1024 + threadIdx.y * 32 + threadIdx.x;
    if (flat < NN) { d_deg[flat] = 1.0f; d_count[flat] = 0; }

    __shared__ float t[32][33];
    int n0 = blockIdx.x * 32, g0 = blockIdx.y * 32;
    int tx = threadIdx.x, ty = threadIdx.y;
    int n = n0 + tx, g = g0 + ty;
    if (n < NN) t[ty][tx] = x[g * NN + n];
    __syncthreads();
    n = n0 + ty; g = g0 + tx;
    if (n < NN) d_xt[n * GG + g] = t[tx][ty];
}

// ---- K_B: single edge pass: ELL build + degree accumulate (1 edge/thread) ----
__global__ void k_build(const int* __restrict__ ei, const float* __restrict__ w) {
    int i = blockIdx.x * blockDim.x + threadIdx.x;
    if (i < EE) {
        int   s  = ei[i];
        int   d  = ei[EE + i];
        float ww = w[i];
        int p = atomicAdd(&d_count[d], 1);
        if (p < WIDTH) d_ell[d * WIDTH + p] = make_float2(__int_as_float(s), ww);
        atomicAdd(&d_deg[d], ww);      // no return use -> REDG
    }
}

// ---- static 8-edge block: 8 shfl-broadcasts -> up to 8 PREDICATED gathers -> FMAs ----
// Predicate (lb+k < cnt) is warp-uniform: no divergence, and a predicated-off
// LDG issues in 1 slot with ZERO L1tex wavefronts (the previous version paid
// 8 wavefronts per padded gather). All 8 loads remain independent/front-batched.
__device__ __forceinline__ void chunk8(const float2* __restrict__ in2, int lane, int cnt,
                                       float2& acc, float ex, float ey, int lb) {
    int   s[8];
    float n[8];
    #pragma unroll
    for (int k = 0; k < 8; k++) {
        s[k] = __float_as_int(__shfl_sync(0xffffffffu, ex, lb + k));
        n[k] = __shfl_sync(0xffffffffu, ey, lb + k);
    }
    float2 v[8];
    #pragma unroll
    for (int k = 0; k < 8; k++) {
        v[k] = make_float2(0.f, 0.f);
        if (lb + k < cnt) v[k] = in2[s[k] * 32 + lane];   // @P LDG.64, uniform pred
    }
    #pragma unroll
    for (int k = 0; k < 8; k++) {
        acc.x = fmaf(n[k], v[k].x, acc.x);
        acc.y = fmaf(n[k], v[k].y, acc.y);
    }
}

// ---- SpMV: warp-per-row, 2 replicas/lane, register-staged ELL, straight-line ----
// Low half (slots 0..31) processed with no branches, per-gather uniform
// predication. Hi half (slots 32..63) guarded; ~0.01% of rows take it.
// LAYER 1 additionally performs the gcn normalization in registers and writes
// the normalized ELL back for LAYER 2.
template <int LAYER>
__global__ void k_spmv(const float* __restrict__ Wa, const float* __restrict__ ba,
                       const float* __restrict__ Wb, const float* __restrict__ b2) {
    __shared__ float sW1[HH], sB1[HH], sW2[HH];
    if (LAYER == 1) {
        if (threadIdx.x < HH) {
            sW1[threadIdx.x] = Wa[threadIdx.x];
            sB1[threadIdx.x] = ba[threadIdx.x];
            sW2[threadIdx.x] = Wb[threadIdx.x];
        }
        __syncthreads();
    }

    int row  = (blockIdx.x * blockDim.x + threadIdx.x) >> 5;   // grid = exactly NN warps
    int lane = threadIdx.x & 31;
    const float2* in2 = (const float2*)(LAYER == 1 ? d_xt : d_zt);
    float2*       ou2 = (float2*)      (LAYER == 1 ? d_zt : d_ot);

    float2* ell2 = d_ell + row * WIDTH;
    int cnt = d_count[row];

    float2 elo = ell2[lane];                       // slots 0..31 (coalesced 256B)

    float dr = rsqrtf(d_deg[row]);
    float sn = dr * dr;                            // self-loop norm = 1/deg

    if (LAYER == 1) {
        // normalize staged entries in registers; pad slots: 0 * anything = 0
        elo.y *= rsqrtf(d_deg[__float_as_int(elo.x)]) * dr;
        ell2[lane] = elo;                          // write back for LAYER 2
    }

    float2 xs = in2[row * 32 + lane];
    float2 acc = make_float2(sn * xs.x, sn * xs.y);

    // straight-line low half; padding skipped via uniform predication
    chunk8(in2, lane, cnt, acc, elo.x, elo.y, 0);
    chunk8(in2, lane, cnt, acc, elo.x, elo.y, 8);
    chunk8(in2, lane, cnt, acc, elo.x, elo.y, 16);
    chunk8(in2, lane, cnt, acc, elo.x, elo.y, 24);

    if (cnt > 32) {                                // rare tail (P ~ 1e-4)
        float2 ehi = ell2[32 + lane];
        if (LAYER == 1) {
            ehi.y *= rsqrtf(d_deg[__float_as_int(ehi.x)]) * dr;
            ell2[32 + lane] = ehi;
        }
        int ch = min(cnt, WIDTH) - 32;
        chunk8(in2, lane, ch, acc, ehi.x, ehi.y, 0);
        chunk8(in2, lane, ch, acc, ehi.x, ehi.y, 8);
        chunk8(in2, lane, ch, acc, ehi.x, ehi.y, 16);
        chunk8(in2, lane, ch, acc, ehi.x, ehi.y, 24);
    }

    float2 res;
    if (LAYER == 1) {
        float z0 = 0.f, z1 = 0.f;
        #pragma unroll
        for (int j = 0; j < HH; j++) {
            z0 += fmaxf(fmaf(acc.x, sW1[j], sB1[j]), 0.f) * sW2[j];
            z1 += fmaxf(fmaf(acc.y, sW1[j], sB1[j]), 0.f) * sW2[j];
        }
        res = make_float2(z0, z1);
    } else {
        float bb = __ldg(b2);
        res = make_float2(acc.x + bb, acc.y + bb);
    }
    ou2[row * 32 + lane] = res;
}

// ---- K_F: transpose out (N,G)->(G,N) fused with mask merge (mask is int32) ----
__global__ void k_out(const float* __restrict__ x, const int* __restrict__ mask,
                      float* __restrict__ out) {
    __shared__ float t[32][33];
    int n0 = blockIdx.x * 32, g0 = blockIdx.y * 32;
    int tx = threadIdx.x, ty = threadIdx.y;
    int n = n0 + ty, g = g0 + tx;
    if (n < NN) t[ty][tx] = d_ot[n * GG + g];
    __syncthreads();
    n = n0 + tx; g = g0 + ty;
    if (n < NN) {
        int idx = g * NN + n;
        out[idx] = mask[idx] ? x[idx] : t[tx][ty];
    }
}

extern "C" void kernel_launch(void* const* d_in, const int* in_sizes, int n_in,
                              void* d_out, int out_size) {
    const float* x    = (const float*)d_in[0];
    const int*   mask = (const int*)d_in[1];      // jax bool -> int32 on the wire
    const int*   ei   = (const int*)d_in[2];
    const float* w    = (const float*)d_in[3];
    const float* W1   = (const float*)d_in[4];
    const float* b1   = (const float*)d_in[5];
    const float* W2   = (const float*)d_in[6];
    const float* b2   = (const float*)d_in[7];
    float*       out  = (float*)d_out;

    dim3 tb(32, 32);
    dim3 tg((NN + 31) / 32, GG / 32);
    k_prep<<<tg, tb>>>(x);
    k_build<<<(EE + 255) / 256, 256>>>(ei, w);
    k_spmv<1><<<NN / 8, 256>>>(W1, b1, W2, b2);   // warp-per-row; also normalizes ELL
    k_spmv<2><<<NN / 8, 256>>>(W1, b1, W2, b2);
    k_out<<<tg, tb>>>(x, mask, out);
}